// round 1
// baseline (speedup 1.0000x reference)
#include <cuda_runtime.h>
#include <cuda_bf16.h>
#include <math.h>

// Problem constants
#define MNODES 4096      // nodes per level
#define NLEV   16
#define NTOT   65536     // NLEV * MNODES
#define HID    256
#define PRED   16
#define HEADS  4
#define HD     64
#define LAYERS 3
#define NB     61440     // non-source nodes = NTOT - MNODES
#define LN_EPS 1e-5f

// ---------------- device scratch (allocation-free rule: static globals) ----------
__device__ __align__(16) float g_QZ[(size_t)NB * 512];      // per-layer: [Qh | q@Wc1^T], 126MB
__device__ __align__(16) float g_KV[(size_t)MNODES * 512];  // per-level: [K | V]
__device__ __align__(16) float g_A [(size_t)MNODES * 256];  // attention out (pre W2)
__device__ __align__(16) float g_Zp[(size_t)MNODES * 256];  // z_pre (before +Zq, LN)
__device__ __align__(16) float g_Wkv[LAYERS * 512 * 256];   // [Wk; Wv] stacked
__device__ __align__(16) float g_bkv[LAYERS * 512];
__device__ __align__(16) float g_Wqc[LAYERS * 512 * 256];   // [Wq; Wc1] stacked
__device__ __align__(16) float g_bqc[LAYERS * 512];
__device__ __align__(16) float g_W2 [LAYERS * 256 * 256];   // Wc2 @ Wo
__device__ __align__(16) float g_b2 [LAYERS * 256];         // Wc2 @ bo + bc

// ---------------- weight prep ------------------------------------------------
__global__ void prep_stack(const float* __restrict__ Wq, const float* __restrict__ bq,
                           const float* __restrict__ Wc,
                           const float* __restrict__ Wk, const float* __restrict__ bk,
                           const float* __restrict__ Wv, const float* __restrict__ bv)
{
    int r = blockIdx.x;          // 0..511
    int which = blockIdx.y;      // 0: Wkv, 1: Wqc
    int l = blockIdx.z;
    int t = threadIdx.x;         // 0..255
    if (which == 0) {
        if (r < 256) {
            g_Wkv[((size_t)l*512 + r)*256 + t] = Wk[((size_t)l*256 + r)*256 + t];
            if (t == 0) g_bkv[l*512 + r] = bk[l*256 + r];
        } else {
            g_Wkv[((size_t)l*512 + r)*256 + t] = Wv[((size_t)l*256 + r-256)*256 + t];
            if (t == 0) g_bkv[l*512 + r] = bv[l*256 + r-256];
        }
    } else {
        if (r < 256) {
            g_Wqc[((size_t)l*512 + r)*256 + t] = Wq[((size_t)l*256 + r)*256 + t];
            if (t == 0) g_bqc[l*512 + r] = bq[l*256 + r];
        } else {
            // Wc1 = Wc[l][r-256][0:256], Wc row stride 512
            g_Wqc[((size_t)l*512 + r)*256 + t] = Wc[((size_t)l*256 + (r-256))*512 + t];
            if (t == 0) g_bqc[l*512 + r] = 0.f;
        }
    }
}

// W2[l] = Wc2[l] @ Wo[l]   (Wc2 = Wc[:, 256:512])
__global__ void prep_fold(const float* __restrict__ Wc, const float* __restrict__ Wo)
{
    int l = blockIdx.z;
    int o = blockIdx.y * 16 + threadIdx.y;
    int i = blockIdx.x * 16 + threadIdx.x;
    const float* wc2 = Wc + ((size_t)l*256 + o)*512 + 256;
    float acc = 0.f;
    for (int j = 0; j < 256; j++)
        acc += wc2[j] * Wo[((size_t)l*256 + j)*256 + i];
    g_W2[((size_t)l*256 + o)*256 + i] = acc;
}

__global__ void prep_b2(const float* __restrict__ Wc, const float* __restrict__ bo,
                        const float* __restrict__ bc)
{
    int l = blockIdx.x;
    int o = threadIdx.x;
    const float* wc2 = Wc + ((size_t)l*256 + o)*512 + 256;
    float acc = bc[l*256 + o];
    for (int j = 0; j < 256; j++)
        acc += wc2[j] * bo[l*256 + j];
    g_b2[l*256 + o] = acc;
}

// ---------------- SGEMM: C[M,N] = A[M,K] @ B[N,K]^T + bias -------------------
// BM=BN=64, BK=16, 128 threads, 8x4 micro-tile. All dims multiples of tiles.
__global__ __launch_bounds__(128)
void sgemm_bias(const float* __restrict__ A, int lda,
                const float* __restrict__ B, int ldb,
                const float* __restrict__ bias,
                float* __restrict__ C, int ldc, int Kdim)
{
    __shared__ float As[16][64];
    __shared__ float Bs[16][64];
    const int bm = blockIdx.y * 64;
    const int bn = blockIdx.x * 64;
    const int t  = threadIdx.x;
    const int tx = t & 15;   // n dir
    const int ty = t >> 4;   // m dir
    float acc[8][4];
    #pragma unroll
    for (int i = 0; i < 8; i++)
        #pragma unroll
        for (int j = 0; j < 4; j++) acc[i][j] = 0.f;

    for (int k0 = 0; k0 < Kdim; k0 += 16) {
        #pragma unroll
        for (int lo = 0; lo < 2; lo++) {
            int idx = t * 2 + lo;               // 0..255
            int row = idx >> 2;
            int kc  = (idx & 3) * 4;
            float4 v = *(const float4*)(A + (size_t)(bm + row) * lda + k0 + kc);
            As[kc+0][row] = v.x; As[kc+1][row] = v.y;
            As[kc+2][row] = v.z; As[kc+3][row] = v.w;
        }
        #pragma unroll
        for (int lo = 0; lo < 2; lo++) {
            int idx = t * 2 + lo;
            int row = idx >> 2;
            int kc  = (idx & 3) * 4;
            float4 v = *(const float4*)(B + (size_t)(bn + row) * ldb + k0 + kc);
            Bs[kc+0][row] = v.x; Bs[kc+1][row] = v.y;
            Bs[kc+2][row] = v.z; Bs[kc+3][row] = v.w;
        }
        __syncthreads();
        #pragma unroll
        for (int k = 0; k < 16; k++) {
            float a[8], b[4];
            *(float4*)&a[0] = *(const float4*)&As[k][ty*8];
            *(float4*)&a[4] = *(const float4*)&As[k][ty*8+4];
            *(float4*)&b[0] = *(const float4*)&Bs[k][tx*4];
            #pragma unroll
            for (int i = 0; i < 8; i++)
                #pragma unroll
                for (int j = 0; j < 4; j++)
                    acc[i][j] = fmaf(a[i], b[j], acc[i][j]);
        }
        __syncthreads();
    }
    #pragma unroll
    for (int i = 0; i < 8; i++) {
        size_t row = bm + ty*8 + i;
        #pragma unroll
        for (int j = 0; j < 4; j++) {
            int col = bn + tx*4 + j;
            float v = acc[i][j];
            if (bias) v += bias[col];
            C[row * ldc + col] = v;
        }
    }
}

// ---------------- per-level attention ----------------------------------------
// block = 128 threads (4 warps = 4 heads), one node per block
__global__ __launch_bounds__(128)
void attn_kernel(const int* __restrict__ preds,   // preds for this level: [MNODES, 16]
                 int lv,
                 float* __restrict__ Aout)        // [MNODES, 256]
{
    const int m    = blockIdx.x;
    const int head = threadIdx.x >> 5;
    const int lane = threadIdx.x & 31;

    __shared__ int sp[16];
    if (threadIdx.x < 16)
        sp[threadIdx.x] = preds[m * 16 + threadIdx.x] - lv * MNODES;
    __syncthreads();

    const float* qrow = g_QZ + (size_t)(lv * MNODES + m) * 512 + head * 64;
    float q1 = qrow[lane], q2 = qrow[lane + 32];

    float s[16];
    #pragma unroll
    for (int p = 0; p < 16; p++) {
        const float* krow = g_KV + (size_t)sp[p] * 512 + head * 64;
        float partial = q1 * krow[lane] + q2 * krow[lane + 32];
        #pragma unroll
        for (int o = 16; o; o >>= 1)
            partial += __shfl_xor_sync(0xffffffffu, partial, o);
        s[p] = partial * 0.125f;  // 1/sqrt(64)
    }
    float mx = s[0];
    #pragma unroll
    for (int p = 1; p < 16; p++) mx = fmaxf(mx, s[p]);
    float sum = 0.f;
    #pragma unroll
    for (int p = 0; p < 16; p++) { s[p] = expf(s[p] - mx); sum += s[p]; }
    float inv = 1.f / sum;

    float a1 = 0.f, a2 = 0.f;
    #pragma unroll
    for (int p = 0; p < 16; p++) {
        const float* vrow = g_KV + (size_t)sp[p] * 512 + 256 + head * 64;
        a1 = fmaf(s[p], vrow[lane],      a1);
        a2 = fmaf(s[p], vrow[lane + 32], a2);
    }
    Aout[(size_t)m * 256 + head * 64 + lane]      = a1 * inv;
    Aout[(size_t)m * 256 + head * 64 + lane + 32] = a2 * inv;
}

// ---------------- LN + exact GELU + scatter to output ------------------------
__global__ __launch_bounds__(256)
void ln_gelu(const float* __restrict__ gamma, const float* __restrict__ beta,
             int lv, int l, float* __restrict__ out)
{
    const int m = blockIdx.x;
    const int t = threadIdx.x;
    float z = g_Zp[(size_t)m * 256 + t]
            + g_QZ[(size_t)(lv * MNODES + m) * 512 + 256 + t];

    // block reduce sum / sumsq (8 warps)
    float s1 = z, s2 = z * z;
    #pragma unroll
    for (int o = 16; o; o >>= 1) {
        s1 += __shfl_xor_sync(0xffffffffu, s1, o);
        s2 += __shfl_xor_sync(0xffffffffu, s2, o);
    }
    __shared__ float r1[8], r2[8];
    __shared__ float smu, srstd;
    int warp = t >> 5;
    if ((t & 31) == 0) { r1[warp] = s1; r2[warp] = s2; }
    __syncthreads();
    if (t == 0) {
        float a = 0.f, b = 0.f;
        #pragma unroll
        for (int w = 0; w < 8; w++) { a += r1[w]; b += r2[w]; }
        float mu  = a * (1.f / 256.f);
        float var = b * (1.f / 256.f) - mu * mu;
        smu = mu; srstd = rsqrtf(var + LN_EPS);
    }
    __syncthreads();
    float zn = (z - smu) * srstd * gamma[t] + beta[t];
    float ge = 0.5f * zn * (1.f + erff(zn * 0.70710678118654752f));
    size_t node = (size_t)(lv + 1) * MNODES + m;
    out[node * 1024 + (size_t)(l + 1) * 256 + t] = ge;
}

// ---------------- level-0 rows of each layer are copied forward ---------------
__global__ __launch_bounds__(256)
void copy_level0(float* __restrict__ out, int l)
{
    int idx = blockIdx.x * 256 + threadIdx.x;   // 4096*256
    int n = idx >> 8;
    int c = idx & 255;
    out[(size_t)n * 1024 + (size_t)(l + 1) * 256 + c] =
        out[(size_t)n * 1024 + (size_t)l * 256 + c];
}

// ---------------- host driver -------------------------------------------------
extern "C" void kernel_launch(void* const* d_in, const int* in_sizes, int n_in,
                              void* d_out, int out_size)
{
    const float* x        = (const float*)d_in[0];
    // d_in[1] edge_index (int64) unused; d_in[2] nodes_lv is arange(M,N) by construction
    const int*   preds_lv = (const int*)d_in[3];
    const float* W_in = (const float*)d_in[4];
    const float* b_in = (const float*)d_in[5];
    const float* Wq   = (const float*)d_in[6];
    const float* bq   = (const float*)d_in[7];
    const float* Wk   = (const float*)d_in[8];
    const float* bk   = (const float*)d_in[9];
    const float* Wv   = (const float*)d_in[10];
    const float* bv   = (const float*)d_in[11];
    const float* Wo   = (const float*)d_in[12];
    const float* bo   = (const float*)d_in[13];
    const float* Wc   = (const float*)d_in[14];
    const float* bc   = (const float*)d_in[15];
    const float* ln_g = (const float*)d_in[16];
    const float* ln_b = (const float*)d_in[17];
    float* out = (float*)d_out;

    float *pQZ, *pKV, *pA, *pZp, *pWkv, *pbkv, *pWqc, *pbqc, *pW2, *pb2;
    cudaGetSymbolAddress((void**)&pQZ,  g_QZ);
    cudaGetSymbolAddress((void**)&pKV,  g_KV);
    cudaGetSymbolAddress((void**)&pA,   g_A);
    cudaGetSymbolAddress((void**)&pZp,  g_Zp);
    cudaGetSymbolAddress((void**)&pWkv, g_Wkv);
    cudaGetSymbolAddress((void**)&pbkv, g_bkv);
    cudaGetSymbolAddress((void**)&pWqc, g_Wqc);
    cudaGetSymbolAddress((void**)&pbqc, g_bqc);
    cudaGetSymbolAddress((void**)&pW2,  g_W2);
    cudaGetSymbolAddress((void**)&pb2,  g_b2);

    // weight prep (cheap; replayed each graph launch — deterministic)
    prep_stack<<<dim3(512, 2, LAYERS), 256>>>(Wq, bq, Wc, Wk, bk, Wv, bv);
    prep_fold<<<dim3(16, 16, LAYERS), dim3(16, 16)>>>(Wc, Wo);
    prep_b2<<<LAYERS, 256>>>(Wc, bo, bc);

    // h0 = x @ W_in^T + b_in  -> out[:, 0:256]
    sgemm_bias<<<dim3(256/64, NTOT/64), 128>>>(x, 256, W_in, 256, b_in,
                                               out, 1024, 256);

    for (int l = 0; l < LAYERS; l++) {
        copy_level0<<<4096, 256>>>(out, l);

        // batched per-layer: [Qh | q@Wc1^T] for all non-source nodes from prev=h_l
        sgemm_bias<<<dim3(512/64, NB/64), 128>>>(
            out + (size_t)MNODES * 1024 + (size_t)l * 256, 1024,
            pWqc + (size_t)l * 512 * 256, 256,
            pbqc + l * 512,
            pQZ, 512, 256);

        for (int lv = 0; lv < NLEV - 1; lv++) {
            // K|V projection of source level lv (from h_{l+1})
            sgemm_bias<<<dim3(512/64, MNODES/64), 128>>>(
                out + (size_t)lv * MNODES * 1024 + (size_t)(l + 1) * 256, 1024,
                pWkv + (size_t)l * 512 * 256, 256,
                pbkv + l * 512,
                pKV, 512, 256);

            attn_kernel<<<MNODES, 128>>>(preds_lv + (size_t)lv * MNODES * 16, lv, pA);

            // z_pre = attnout @ W2^T + b2
            sgemm_bias<<<dim3(256/64, MNODES/64), 128>>>(
                pA, 256,
                pW2 + (size_t)l * 256 * 256, 256,
                pb2 + l * 256,
                pZp, 256, 256);

            ln_gelu<<<MNODES, 256>>>(ln_g + l * 256, ln_b + l * 256, lv, l, out);
        }
    }
}

// round 2
// speedup vs baseline: 1.5580x; 1.5580x over previous
#include <cuda_runtime.h>
#include <cuda_bf16.h>
#include <math.h>
#include <stdint.h>

// Problem constants
#define MNODES 4096
#define NLEV   16
#define NTOT   65536
#define HID    256
#define PRED   16
#define HEADS  4
#define HD     64
#define LAYERS 3
#define NB     61440
#define LN_EPS 1e-5f

// ---------------- device scratch ----------------
__device__ __align__(16) float g_QZ[(size_t)NB * 512];      // per-layer: [Qh | q@Wc1^T]
__device__ __align__(16) float g_KV[(size_t)MNODES * 512];  // per-level: [K | V]
__device__ __align__(16) float g_A [(size_t)MNODES * 256];  // attention out (pre W2)
__device__ __align__(16) float g_Wkv[LAYERS * 512 * 256];
__device__ __align__(16) float g_bkv[LAYERS * 512];
__device__ __align__(16) float g_Wqc[LAYERS * 512 * 256];
__device__ __align__(16) float g_bqc[LAYERS * 512];
__device__ __align__(16) float g_W2 [LAYERS * 256 * 256];   // Wc2 @ Wo
__device__ __align__(16) float g_b2 [LAYERS * 256];         // Wc2 @ bo + bc

// ---------------- helpers ----------------
__device__ __forceinline__ uint32_t cvt_tf32(float x) {
    uint32_t r; asm("cvt.rna.tf32.f32 %0, %1;" : "=r"(r) : "f"(x)); return r;
}
__device__ __forceinline__ void mma_tf32(float c[4], const uint4& a, const uint2& b) {
    asm volatile(
        "mma.sync.aligned.m16n8k8.row.col.f32.tf32.tf32.f32 "
        "{%0,%1,%2,%3}, {%4,%5,%6,%7}, {%8,%9}, {%0,%1,%2,%3};"
        : "+f"(c[0]), "+f"(c[1]), "+f"(c[2]), "+f"(c[3])
        : "r"(a.x), "r"(a.y), "r"(a.z), "r"(a.w), "r"(b.x), "r"(b.y));
}

// ---------------- weight prep ----------------
__global__ void prep_stack(const float* __restrict__ Wq, const float* __restrict__ bq,
                           const float* __restrict__ Wc,
                           const float* __restrict__ Wk, const float* __restrict__ bk,
                           const float* __restrict__ Wv, const float* __restrict__ bv)
{
    int r = blockIdx.x, which = blockIdx.y, l = blockIdx.z, t = threadIdx.x;
    if (which == 0) {
        if (r < 256) {
            g_Wkv[((size_t)l*512 + r)*256 + t] = Wk[((size_t)l*256 + r)*256 + t];
            if (t == 0) g_bkv[l*512 + r] = bk[l*256 + r];
        } else {
            g_Wkv[((size_t)l*512 + r)*256 + t] = Wv[((size_t)l*256 + r-256)*256 + t];
            if (t == 0) g_bkv[l*512 + r] = bv[l*256 + r-256];
        }
    } else {
        if (r < 256) {
            g_Wqc[((size_t)l*512 + r)*256 + t] = Wq[((size_t)l*256 + r)*256 + t];
            if (t == 0) g_bqc[l*512 + r] = bq[l*256 + r];
        } else {
            g_Wqc[((size_t)l*512 + r)*256 + t] = Wc[((size_t)l*256 + (r-256))*512 + t];
            if (t == 0) g_bqc[l*512 + r] = 0.f;
        }
    }
}

__global__ void prep_fold(const float* __restrict__ Wc, const float* __restrict__ Wo)
{
    int l = blockIdx.z;
    int o = blockIdx.y * 16 + threadIdx.y;
    int i = blockIdx.x * 16 + threadIdx.x;
    const float* wc2 = Wc + ((size_t)l*256 + o)*512 + 256;
    float acc = 0.f;
    for (int j = 0; j < 256; j++)
        acc += wc2[j] * Wo[((size_t)l*256 + j)*256 + i];
    g_W2[((size_t)l*256 + o)*256 + i] = acc;
}

__global__ void prep_b2(const float* __restrict__ Wc, const float* __restrict__ bo,
                        const float* __restrict__ bc)
{
    int l = blockIdx.x, o = threadIdx.x;
    const float* wc2 = Wc + ((size_t)l*256 + o)*512 + 256;
    float acc = bc[l*256 + o];
    for (int j = 0; j < 256; j++)
        acc += wc2[j] * bo[l*256 + j];
    g_b2[l*256 + o] = acc;
}

// =====================================================================
// TF32 tensor-core GEMM:  C[M,N] = A[M,K=256] @ B[N,K=256]^T + bias
// BN=64, BK=32.  BM=128 -> 256 thr (8 warps 4x2), BM=64 -> 128 thr (4 warps 2x2).
// Smem holds fragment-permuted tf32 so the mainloop does LDS.128/LDS.64 only.
// =====================================================================
template<int BM, int NT>
__global__ __launch_bounds__(NT)
void gemm_tf32(const float* __restrict__ A, int lda,
               const float* __restrict__ B, int ldb,
               const float* __restrict__ bias,
               float* __restrict__ C, int ldc)
{
    constexpr int AF4 = BM * 8 / NT;   // float4 loads per thread for A tile (BM x 32)
    constexpr int BF4 = 64 * 8 / NT;   // for B tile (64 x 32)
    constexpr int ASZ = BM * 32;       // u32 per buffer
    constexpr int BSZ = 64 * 32;
    extern __shared__ uint32_t sm[];
    uint32_t* As = sm;
    uint32_t* Bs = sm + 2 * ASZ;

    const int t = threadIdx.x;
    const int lane = t & 31, warp = t >> 5;
    const int warpN = warp & 1, warpM = warp >> 1;
    const int gid = lane >> 2, tig = lane & 3;
    const int bm = blockIdx.y * BM;
    const int bn = blockIdx.x * 64;

    const float* Ag = A + (size_t)bm * lda;
    const float* Bg = B + (size_t)bn * ldb;

    float acc[2][4][4];
    #pragma unroll
    for (int i = 0; i < 2; i++)
        #pragma unroll
        for (int j = 0; j < 4; j++)
            #pragma unroll
            for (int q = 0; q < 4; q++) acc[i][j][q] = 0.f;

    float4 aR[AF4], bR[BF4];

    auto loadG = [&](int k0) {
        #pragma unroll
        for (int i = 0; i < AF4; i++) {
            int f4 = t + i * NT;
            aR[i] = *(const float4*)(Ag + (size_t)(f4 >> 3) * lda + k0 + (f4 & 7) * 4);
        }
        #pragma unroll
        for (int i = 0; i < BF4; i++) {
            int f4 = t + i * NT;
            bR[i] = *(const float4*)(Bg + (size_t)(f4 >> 3) * ldb + k0 + (f4 & 7) * 4);
        }
    };
    auto storeS = [&](int buf) {
        uint32_t* Ad = As + buf * ASZ;
        uint32_t* Bd = Bs + buf * BSZ;
        #pragma unroll
        for (int i = 0; i < AF4; i++) {
            int f4 = t + i * NT;
            int row = f4 >> 3, kc4 = f4 & 7;
            int grp = (row >> 4) * 4 + (kc4 >> 1);
            int j   = ((row >> 3) & 1) + 2 * (kc4 & 1);
            uint32_t* p = Ad + (grp * 32 + (row & 7) * 4) * 4 + j;
            p[0]  = cvt_tf32(aR[i].x);
            p[4]  = cvt_tf32(aR[i].y);
            p[8]  = cvt_tf32(aR[i].z);
            p[12] = cvt_tf32(aR[i].w);
        }
        #pragma unroll
        for (int i = 0; i < BF4; i++) {
            int f4 = t + i * NT;
            int n = f4 >> 3, kc4 = f4 & 7;
            int grp = (n >> 3) * 4 + (kc4 >> 1);
            int j   = kc4 & 1;
            uint32_t* p = Bd + (grp * 32 + (n & 7) * 4) * 2 + j;
            p[0] = cvt_tf32(bR[i].x);
            p[2] = cvt_tf32(bR[i].y);
            p[4] = cvt_tf32(bR[i].z);
            p[6] = cvt_tf32(bR[i].w);
        }
    };
    auto compute = [&](int buf) {
        const uint4* A4 = (const uint4*)(As + buf * ASZ);
        const uint2* B2 = (const uint2*)(Bs + buf * BSZ);
        #pragma unroll
        for (int ks = 0; ks < 4; ks++) {
            uint4 a[2]; uint2 b[4];
            #pragma unroll
            for (int mf = 0; mf < 2; mf++)
                a[mf] = A4[((warpM * 2 + mf) * 4 + ks) * 32 + lane];
            #pragma unroll
            for (int nf = 0; nf < 4; nf++)
                b[nf] = B2[((warpN * 4 + nf) * 4 + ks) * 32 + lane];
            #pragma unroll
            for (int mf = 0; mf < 2; mf++)
                #pragma unroll
                for (int nf = 0; nf < 4; nf++)
                    mma_tf32(acc[mf][nf], a[mf], b[nf]);
        }
    };

    loadG(0);
    storeS(0);
    __syncthreads();
    #pragma unroll 1
    for (int it = 0; it < 8; it++) {
        int cur = it & 1;
        if (it < 7) loadG((it + 1) * 32);
        compute(cur);
        if (it < 7) {
            storeS(1 - cur);
            __syncthreads();
        }
    }

    #pragma unroll
    for (int mf = 0; mf < 2; mf++) {
        int r0 = bm + warpM * 32 + mf * 16 + gid;
        #pragma unroll
        for (int nf = 0; nf < 4; nf++) {
            int c0 = bn + warpN * 32 + nf * 8 + tig * 2;
            float bx = bias ? bias[c0] : 0.f, by = bias ? bias[c0 + 1] : 0.f;
            float2 v0 = make_float2(acc[mf][nf][0] + bx, acc[mf][nf][1] + by);
            float2 v1 = make_float2(acc[mf][nf][2] + bx, acc[mf][nf][3] + by);
            *(float2*)(C + (size_t)r0 * ldc + c0)       = v0;
            *(float2*)(C + (size_t)(r0 + 8) * ldc + c0) = v1;
        }
    }
}

// =====================================================================
// Fused: Zp = A @ W2^T + b2 + Zq ;  LayerNorm ;  GELU ;  scatter to out.
// BM=32 rows, BN=256 (full row in block) -> LN is an in-block reduction.
// 256 thr = 8 warps, all in n-direction (warp tile 32x32).
// =====================================================================
__global__ __launch_bounds__(256)
void zln_kernel(const float* __restrict__ A,      // [4096,256] attn out
                const float* __restrict__ B,      // W2 layer l [256,256]
                const float* __restrict__ b2,     // [256]
                const float* __restrict__ Zq,     // pQZ + lv*4096*512 + 256
                const float* __restrict__ gma,
                const float* __restrict__ bta,
                float* __restrict__ outp)         // out + (lv+1)*M*1024 + (l+1)*256
{
    constexpr int ASZ = 32 * 32;     // u32 per buffer
    constexpr int BSZ = 256 * 32;
    extern __shared__ uint32_t sm[];
    uint32_t* As = sm;
    uint32_t* Bs = sm + 2 * ASZ;
    __shared__ float redA[32][8], redB[32][8];

    const int t = threadIdx.x;
    const int lane = t & 31, warpN = t >> 5;
    const int gid = lane >> 2, tig = lane & 3;
    const int bm = blockIdx.x * 32;

    const float* Ag = A + (size_t)bm * 256;

    float acc[2][4][4];
    #pragma unroll
    for (int i = 0; i < 2; i++)
        #pragma unroll
        for (int j = 0; j < 4; j++)
            #pragma unroll
            for (int q = 0; q < 4; q++) acc[i][j][q] = 0.f;

    float4 aR; float4 bR[8];
    auto loadG = [&](int k0) {
        aR = *(const float4*)(Ag + (size_t)(t >> 3) * 256 + k0 + (t & 7) * 4);
        #pragma unroll
        for (int i = 0; i < 8; i++) {
            int f4 = t + i * 256;
            bR[i] = *(const float4*)(B + (size_t)(f4 >> 3) * 256 + k0 + (f4 & 7) * 4);
        }
    };
    auto storeS = [&](int buf) {
        uint32_t* Ad = As + buf * ASZ;
        uint32_t* Bd = Bs + buf * BSZ;
        {
            int row = t >> 3, kc4 = t & 7;
            int grp = (row >> 4) * 4 + (kc4 >> 1);
            int j   = ((row >> 3) & 1) + 2 * (kc4 & 1);
            uint32_t* p = Ad + (grp * 32 + (row & 7) * 4) * 4 + j;
            p[0] = cvt_tf32(aR.x); p[4] = cvt_tf32(aR.y);
            p[8] = cvt_tf32(aR.z); p[12] = cvt_tf32(aR.w);
        }
        #pragma unroll
        for (int i = 0; i < 8; i++) {
            int f4 = t + i * 256;
            int n = f4 >> 3, kc4 = f4 & 7;
            int grp = (n >> 3) * 4 + (kc4 >> 1);
            int j   = kc4 & 1;
            uint32_t* p = Bd + (grp * 32 + (n & 7) * 4) * 2 + j;
            p[0] = cvt_tf32(bR[i].x); p[2] = cvt_tf32(bR[i].y);
            p[4] = cvt_tf32(bR[i].z); p[6] = cvt_tf32(bR[i].w);
        }
    };
    auto compute = [&](int buf) {
        const uint4* A4 = (const uint4*)(As + buf * ASZ);
        const uint2* B2 = (const uint2*)(Bs + buf * BSZ);
        #pragma unroll
        for (int ks = 0; ks < 4; ks++) {
            uint4 a[2]; uint2 b[4];
            #pragma unroll
            for (int mf = 0; mf < 2; mf++)
                a[mf] = A4[(mf * 4 + ks) * 32 + lane];
            #pragma unroll
            for (int nf = 0; nf < 4; nf++)
                b[nf] = B2[((warpN * 4 + nf) * 4 + ks) * 32 + lane];
            #pragma unroll
            for (int mf = 0; mf < 2; mf++)
                #pragma unroll
                for (int nf = 0; nf < 4; nf++)
                    mma_tf32(acc[mf][nf], a[mf], b[nf]);
        }
    };

    loadG(0);
    storeS(0);
    __syncthreads();
    #pragma unroll 1
    for (int it = 0; it < 8; it++) {
        int cur = it & 1;
        if (it < 7) loadG((it + 1) * 32);
        compute(cur);
        if (it < 7) {
            storeS(1 - cur);
            __syncthreads();
        }
    }

    // --- epilogue: add b2 + Zq, giving z in regs ---
    #pragma unroll
    for (int mf = 0; mf < 2; mf++) {
        int mlo = bm + mf * 16 + gid;
        int mhi = mlo + 8;
        #pragma unroll
        for (int nf = 0; nf < 4; nf++) {
            int col = warpN * 32 + nf * 8 + tig * 2;
            float b0 = b2[col], b1 = b2[col + 1];
            float2 zl = *(const float2*)(Zq + (size_t)mlo * 512 + col);
            float2 zh = *(const float2*)(Zq + (size_t)mhi * 512 + col);
            acc[mf][nf][0] += b0 + zl.x;
            acc[mf][nf][1] += b1 + zl.y;
            acc[mf][nf][2] += b0 + zh.x;
            acc[mf][nf][3] += b1 + zh.y;
        }
    }
    // --- LN reduction ---
    #pragma unroll
    for (int mf = 0; mf < 2; mf++)
        #pragma unroll
        for (int rh = 0; rh < 2; rh++) {
            float s1 = 0.f, s2 = 0.f;
            #pragma unroll
            for (int nf = 0; nf < 4; nf++) {
                float z0 = acc[mf][nf][2 * rh], z1 = acc[mf][nf][2 * rh + 1];
                s1 += z0 + z1;
                s2 += z0 * z0 + z1 * z1;
            }
            s1 += __shfl_xor_sync(0xffffffffu, s1, 1);
            s2 += __shfl_xor_sync(0xffffffffu, s2, 1);
            s1 += __shfl_xor_sync(0xffffffffu, s1, 2);
            s2 += __shfl_xor_sync(0xffffffffu, s2, 2);
            if (tig == 0) {
                int rowL = mf * 16 + rh * 8 + gid;
                redA[rowL][warpN] = s1;
                redB[rowL][warpN] = s2;
            }
        }
    __syncthreads();
    #pragma unroll
    for (int mf = 0; mf < 2; mf++)
        #pragma unroll
        for (int rh = 0; rh < 2; rh++) {
            int rowL = mf * 16 + rh * 8 + gid;
            float a = 0.f, b = 0.f;
            #pragma unroll
            for (int w = 0; w < 8; w++) { a += redA[rowL][w]; b += redB[rowL][w]; }
            float mu   = a * (1.f / 256.f);
            float var  = b * (1.f / 256.f) - mu * mu;
            float rstd = rsqrtf(var + LN_EPS);
            size_t rbase = (size_t)(bm + rowL) * 1024;
            #pragma unroll
            for (int nf = 0; nf < 4; nf++) {
                int col = warpN * 32 + nf * 8 + tig * 2;
                float z0 = (acc[mf][nf][2 * rh]     - mu) * rstd * gma[col]     + bta[col];
                float z1 = (acc[mf][nf][2 * rh + 1] - mu) * rstd * gma[col + 1] + bta[col + 1];
                float g0 = 0.5f * z0 * (1.f + erff(z0 * 0.70710678118654752f));
                float g1 = 0.5f * z1 * (1.f + erff(z1 * 0.70710678118654752f));
                *(float2*)(outp + rbase + col) = make_float2(g0, g1);
            }
        }
}

// ---------------- per-level attention (unchanged) ----------------
__global__ __launch_bounds__(128)
void attn_kernel(const int* __restrict__ preds, int lv, float* __restrict__ Aout)
{
    const int m = blockIdx.x;
    const int head = threadIdx.x >> 5;
    const int lane = threadIdx.x & 31;

    __shared__ int sp[16];
    if (threadIdx.x < 16)
        sp[threadIdx.x] = preds[m * 16 + threadIdx.x] - lv * MNODES;
    __syncthreads();

    const float* qrow = g_QZ + (size_t)(lv * MNODES + m) * 512 + head * 64;
    float q1 = qrow[lane], q2 = qrow[lane + 32];

    float s[16];
    #pragma unroll
    for (int p = 0; p < 16; p++) {
        const float* krow = g_KV + (size_t)sp[p] * 512 + head * 64;
        float partial = q1 * krow[lane] + q2 * krow[lane + 32];
        #pragma unroll
        for (int o = 16; o; o >>= 1)
            partial += __shfl_xor_sync(0xffffffffu, partial, o);
        s[p] = partial * 0.125f;
    }
    float mx = s[0];
    #pragma unroll
    for (int p = 1; p < 16; p++) mx = fmaxf(mx, s[p]);
    float sum = 0.f;
    #pragma unroll
    for (int p = 0; p < 16; p++) { s[p] = expf(s[p] - mx); sum += s[p]; }
    float inv = 1.f / sum;

    float a1 = 0.f, a2 = 0.f;
    #pragma unroll
    for (int p = 0; p < 16; p++) {
        const float* vrow = g_KV + (size_t)sp[p] * 512 + 256 + head * 64;
        a1 = fmaf(s[p], vrow[lane],      a1);
        a2 = fmaf(s[p], vrow[lane + 32], a2);
    }
    Aout[(size_t)m * 256 + head * 64 + lane]      = a1 * inv;
    Aout[(size_t)m * 256 + head * 64 + lane + 32] = a2 * inv;
}

__global__ __launch_bounds__(256)
void copy_level0(float* __restrict__ out, int l)
{
    int idx = blockIdx.x * 256 + threadIdx.x;
    int n = idx >> 8, c = idx & 255;
    out[(size_t)n * 1024 + (size_t)(l + 1) * 256 + c] =
        out[(size_t)n * 1024 + (size_t)l * 256 + c];
}

// ---------------- host driver ----------------
extern "C" void kernel_launch(void* const* d_in, const int* in_sizes, int n_in,
                              void* d_out, int out_size)
{
    const float* x        = (const float*)d_in[0];
    const int*   preds_lv = (const int*)d_in[3];
    const float* W_in = (const float*)d_in[4];
    const float* b_in = (const float*)d_in[5];
    const float* Wq   = (const float*)d_in[6];
    const float* bq   = (const float*)d_in[7];
    const float* Wk   = (const float*)d_in[8];
    const float* bk   = (const float*)d_in[9];
    const float* Wv   = (const float*)d_in[10];
    const float* bv   = (const float*)d_in[11];
    const float* Wo   = (const float*)d_in[12];
    const float* bo   = (const float*)d_in[13];
    const float* Wc   = (const float*)d_in[14];
    const float* bc   = (const float*)d_in[15];
    const float* ln_g = (const float*)d_in[16];
    const float* ln_b = (const float*)d_in[17];
    float* out = (float*)d_out;

    float *pQZ, *pKV, *pA, *pWkv, *pbkv, *pWqc, *pbqc, *pW2, *pb2;
    cudaGetSymbolAddress((void**)&pQZ,  g_QZ);
    cudaGetSymbolAddress((void**)&pKV,  g_KV);
    cudaGetSymbolAddress((void**)&pA,   g_A);
    cudaGetSymbolAddress((void**)&pWkv, g_Wkv);
    cudaGetSymbolAddress((void**)&pbkv, g_bkv);
    cudaGetSymbolAddress((void**)&pWqc, g_Wqc);
    cudaGetSymbolAddress((void**)&pbqc, g_bqc);
    cudaGetSymbolAddress((void**)&pW2,  g_W2);
    cudaGetSymbolAddress((void**)&pb2,  g_b2);

    static bool attr_done = false;
    if (!attr_done) {
        cudaFuncSetAttribute((const void*)gemm_tf32<128,256>,
                             cudaFuncAttributeMaxDynamicSharedMemorySize, 49152);
        cudaFuncSetAttribute((const void*)gemm_tf32<64,128>,
                             cudaFuncAttributeMaxDynamicSharedMemorySize, 32768);
        cudaFuncSetAttribute((const void*)zln_kernel,
                             cudaFuncAttributeMaxDynamicSharedMemorySize, 73728);
        attr_done = true;
    }

    prep_stack<<<dim3(512, 2, LAYERS), 256>>>(Wq, bq, Wc, Wk, bk, Wv, bv);
    prep_fold<<<dim3(16, 16, LAYERS), dim3(16, 16)>>>(Wc, Wo);
    prep_b2<<<LAYERS, 256>>>(Wc, bo, bc);

    // h0 = x @ W_in^T + b_in -> out[:, 0:256]
    gemm_tf32<128,256><<<dim3(256/64, NTOT/128), 256, 49152>>>(
        x, 256, W_in, 256, b_in, out, 1024);

    for (int l = 0; l < LAYERS; l++) {
        copy_level0<<<4096, 256>>>(out, l);

        // [Qh | q@Wc1^T] for all non-source nodes from h_l
        gemm_tf32<128,256><<<dim3(512/64, NB/128), 256, 49152>>>(
            out + (size_t)MNODES * 1024 + (size_t)l * 256, 1024,
            pWqc + (size_t)l * 512 * 256, 256,
            pbqc + l * 512,
            pQZ, 512);

        for (int lv = 0; lv < NLEV - 1; lv++) {
            // K|V projection of source level lv (from h_{l+1})
            gemm_tf32<64,128><<<dim3(512/64, MNODES/64), 128, 32768>>>(
                out + (size_t)lv * MNODES * 1024 + (size_t)(l + 1) * 256, 1024,
                pWkv + (size_t)l * 512 * 256, 256,
                pbkv + l * 512,
                pKV, 512);

            attn_kernel<<<MNODES, 128>>>(preds_lv + (size_t)lv * MNODES * 16, lv, pA);

            // fused: Zp GEMM + residual + LN + GELU -> out rows of level lv+1
            zln_kernel<<<MNODES/32, 256, 73728>>>(
                pA,
                pW2 + (size_t)l * 256 * 256,
                pb2 + l * 256,
                pQZ + (size_t)lv * MNODES * 512 + 256,
                ln_g + l * 256, ln_b + l * 256,
                out + (size_t)(lv + 1) * MNODES * 1024 + (size_t)(l + 1) * 256);
        }
    }
}

// round 6
// speedup vs baseline: 1.8633x; 1.1959x over previous
#include <cuda_runtime.h>
#include <cuda_bf16.h>
#include <math.h>
#include <stdint.h>

#define MNODES 4096
#define NLEV   16
#define NTOT   65536
#define HID    256
#define PRED   16
#define HEADS  4
#define HD     64
#define LAYERS 3
#define NB     61440
#define LN_EPS 1e-5f

// ---------------- device scratch ----------------
__device__ __align__(16) float    g_QZ[(size_t)NB * 512];        // [Qh | q@Wc1^T] fp32
__device__ __align__(16) float    g_KV[2][(size_t)MNODES * 512]; // ping-pong [K|V] fp32
__device__ __align__(16) uint32_t g_Xp[(size_t)NTOT * 256];      // x permuted tf32
__device__ __align__(16) uint32_t g_Hp[(size_t)NB * 256];        // h_l rows 4096.. permuted
__device__ __align__(16) uint32_t g_Hp0[(size_t)MNODES * 256];   // h level-0 rows permuted
__device__ __align__(16) float    g_Wkv[LAYERS * 512 * 256];     // stacked fp32 (staging)
__device__ __align__(16) float    g_bkv[LAYERS * 512];
__device__ __align__(16) float    g_Wqc[LAYERS * 512 * 256];
__device__ __align__(16) float    g_bqc[LAYERS * 512];
__device__ __align__(16) float    g_W2 [LAYERS * 256 * 256];
__device__ __align__(16) float    g_b2 [LAYERS * 256];
__device__ __align__(16) uint32_t g_Wkvp[LAYERS * 512 * 256];    // permuted tf32
__device__ __align__(16) uint32_t g_Wqcp[LAYERS * 512 * 256];
__device__ __align__(16) uint32_t g_W2p [LAYERS * 256 * 256];
__device__ __align__(16) uint32_t g_Winp[256 * 256];

// ---------------- helpers ----------------
__device__ __forceinline__ uint32_t cvt_tf32(float x) {
    uint32_t r; asm("cvt.rna.tf32.f32 %0, %1;" : "=r"(r) : "f"(x)); return r;
}
__device__ __forceinline__ void mma_tf32(float c[4], const uint4& a, const uint2& b) {
    asm volatile(
        "mma.sync.aligned.m16n8k8.row.col.f32.tf32.tf32.f32 "
        "{%0,%1,%2,%3}, {%4,%5,%6,%7}, {%8,%9}, {%0,%1,%2,%3};"
        : "+f"(c[0]), "+f"(c[1]), "+f"(c[2]), "+f"(c[3])
        : "r"(a.x), "r"(a.y), "r"(a.z), "r"(a.w), "r"(b.x), "r"(b.y));
}
// permuted A layout (u32 index) for element (row, k), K=256 total
__device__ __forceinline__ int pidx(int row, int k, int mgTot) {
    int kc = k >> 5, ks = (k >> 3) & 3;
    return ((kc * mgTot + (row >> 4)) * 4 + ks) * 128
         + (row & 7) * 16 + (k & 3) * 4 + ((row >> 3) & 1) + 2 * ((k >> 2) & 1);
}
// permuted B layout (u32 index) for element (n, k)
__device__ __forceinline__ int bidx(int n, int k, int ngTot) {
    int kc = k >> 5, ks = (k >> 3) & 3;
    return (((kc * ngTot + (n >> 3)) * 4 + ks) * 32 + (n & 7) * 4 + (k & 3)) * 2
         + ((k >> 2) & 1);
}

// ---------------- weight prep ----------------
__global__ void prep_stack(const float* __restrict__ Wq, const float* __restrict__ bq,
                           const float* __restrict__ Wc,
                           const float* __restrict__ Wk, const float* __restrict__ bk,
                           const float* __restrict__ Wv, const float* __restrict__ bv)
{
    int r = blockIdx.x, which = blockIdx.y, l = blockIdx.z, t = threadIdx.x;
    if (which == 0) {
        if (r < 256) {
            g_Wkv[((size_t)l*512 + r)*256 + t] = Wk[((size_t)l*256 + r)*256 + t];
            if (t == 0) g_bkv[l*512 + r] = bk[l*256 + r];
        } else {
            g_Wkv[((size_t)l*512 + r)*256 + t] = Wv[((size_t)l*256 + r-256)*256 + t];
            if (t == 0) g_bkv[l*512 + r] = bv[l*256 + r-256];
        }
    } else {
        if (r < 256) {
            g_Wqc[((size_t)l*512 + r)*256 + t] = Wq[((size_t)l*256 + r)*256 + t];
            if (t == 0) g_bqc[l*512 + r] = bq[l*256 + r];
        } else {
            g_Wqc[((size_t)l*512 + r)*256 + t] = Wc[((size_t)l*256 + (r-256))*512 + t];
            if (t == 0) g_bqc[l*512 + r] = 0.f;
        }
    }
}
__global__ void prep_fold(const float* __restrict__ Wc, const float* __restrict__ Wo)
{
    int l = blockIdx.z;
    int o = blockIdx.y * 16 + threadIdx.y;
    int i = blockIdx.x * 16 + threadIdx.x;
    const float* wc2 = Wc + ((size_t)l*256 + o)*512 + 256;
    float acc = 0.f;
    for (int j = 0; j < 256; j++)
        acc += wc2[j] * Wo[((size_t)l*256 + j)*256 + i];
    g_W2[((size_t)l*256 + o)*256 + i] = acc;
}
__global__ void prep_b2(const float* __restrict__ Wc, const float* __restrict__ bo,
                        const float* __restrict__ bc)
{
    int l = blockIdx.x, o = threadIdx.x;
    const float* wc2 = Wc + ((size_t)l*256 + o)*512 + 256;
    float acc = bc[l*256 + o];
    for (int j = 0; j < 256; j++)
        acc += wc2[j] * bo[l*256 + j];
    g_b2[l*256 + o] = acc;
}
// permute a [N,256] fp32 row-major weight into tf32 fragment order
__global__ void permW(const float* __restrict__ src, uint32_t* __restrict__ dst,
                      int N, int ngTot, int srcStride, int dstStride)
{
    int l = blockIdx.y;
    int idx = blockIdx.x * 256 + threadIdx.x;
    if (idx >= N * 256) return;
    int n = idx >> 8, k = idx & 255;
    dst[(size_t)l * dstStride + bidx(n, k, ngTot)] =
        cvt_tf32(src[(size_t)l * srcStride + (size_t)n * 256 + k]);
}
// permute activations [M,256] fp32 into tf32 fragment order
__global__ void permX(const float* __restrict__ src, uint32_t* __restrict__ dst, int mgTot)
{
    int idx = blockIdx.x * 256 + threadIdx.x;
    int row = idx >> 8, k = idx & 255;
    dst[pidx(row, k, mgTot)] = cvt_tf32(src[(size_t)row * 256 + k]);
}

// =====================================================================
// GEMM on pre-permuted operands: C[M,N] = A @ B^T + bias
// BM=128, BN=64, 256 thr (8 warps, 4M x 2N). Smem staging = plain uint4 copies.
// Optional permuted-A outputs (row<4096 -> P0, else P1).
// =====================================================================
__global__ __launch_bounds__(256)
void gemm_perm(const uint32_t* __restrict__ Ap, int mgTot,
               const uint32_t* __restrict__ Bp, int ngTot,
               const float* __restrict__ bias,
               float* __restrict__ C, int ldc,
               uint32_t* __restrict__ P0, uint32_t* __restrict__ P1)
{
    __shared__ uint32_t As[2][4096];
    __shared__ uint32_t Bs[2][2048];
    const int t = threadIdx.x, lane = t & 31, warp = t >> 5;
    const int warpN = warp & 1, warpM = warp >> 1;
    const int gid = lane >> 2, tig = lane & 3;
    const int bm = blockIdx.y * 128, bn = blockIdx.x * 64;
    const int mg0 = bm >> 4, ng0 = bn >> 3;

    float acc[2][4][4];
    #pragma unroll
    for (int i = 0; i < 2; i++)
        #pragma unroll
        for (int j = 0; j < 4; j++)
            #pragma unroll
            for (int q = 0; q < 4; q++) acc[i][j][q] = 0.f;

    uint4 aR[4], bR[2];
    auto loadG = [&](int kc) {
        #pragma unroll
        for (int i = 0; i < 4; i++) {
            int idx = t + i * 256;
            int mgl = idx >> 7, r = idx & 127;
            aR[i] = ((const uint4*)Ap)[(size_t)(kc * mgTot + mg0 + mgl) * 128 + r];
        }
        #pragma unroll
        for (int i = 0; i < 2; i++) {
            int idx = t + i * 256;
            int ngl = idx >> 6, r = idx & 63;
            bR[i] = ((const uint4*)Bp)[(size_t)(kc * ngTot + ng0 + ngl) * 64 + r];
        }
    };
    auto storeS = [&](int buf) {
        #pragma unroll
        for (int i = 0; i < 4; i++) ((uint4*)As[buf])[t + i * 256] = aR[i];
        #pragma unroll
        for (int i = 0; i < 2; i++) ((uint4*)Bs[buf])[t + i * 256] = bR[i];
    };
    auto compute = [&](int buf) {
        #pragma unroll
        for (int ks = 0; ks < 4; ks++) {
            uint4 a[2]; uint2 b[4];
            #pragma unroll
            for (int mf = 0; mf < 2; mf++)
                a[mf] = ((const uint4*)As[buf])[((warpM * 2 + mf) * 4 + ks) * 32 + lane];
            #pragma unroll
            for (int nf = 0; nf < 4; nf++)
                b[nf] = ((const uint2*)Bs[buf])[((warpN * 4 + nf) * 4 + ks) * 32 + lane];
            #pragma unroll
            for (int mf = 0; mf < 2; mf++)
                #pragma unroll
                for (int nf = 0; nf < 4; nf++)
                    mma_tf32(acc[mf][nf], a[mf], b[nf]);
        }
    };

    loadG(0); storeS(0); __syncthreads();
    #pragma unroll 1
    for (int kc = 0; kc < 8; kc++) {
        int cur = kc & 1;
        if (kc < 7) loadG(kc + 1);
        compute(cur);
        if (kc < 7) { storeS(1 - cur); __syncthreads(); }
    }

    #pragma unroll
    for (int mf = 0; mf < 2; mf++) {
        int r0 = bm + warpM * 32 + mf * 16 + gid;
        #pragma unroll
        for (int nf = 0; nf < 4; nf++) {
            int c0 = bn + warpN * 32 + nf * 8 + tig * 2;
            float bx = bias ? bias[c0] : 0.f, by = bias ? bias[c0 + 1] : 0.f;
            float v00 = acc[mf][nf][0] + bx, v01 = acc[mf][nf][1] + by;
            float v10 = acc[mf][nf][2] + bx, v11 = acc[mf][nf][3] + by;
            *(float2*)(C + (size_t)r0 * ldc + c0)       = make_float2(v00, v01);
            *(float2*)(C + (size_t)(r0 + 8) * ldc + c0) = make_float2(v10, v11);
            if (P0) {
                uint32_t* P = (r0 < 4096) ? P0 : P1;
                int rr   = (r0 < 4096) ? r0 : r0 - 4096;
                int mgT  = (r0 < 4096) ? 256 : 3840;
                int base = pidx(rr, c0, mgT);
                P[base]     = cvt_tf32(v00);
                P[base + 4] = cvt_tf32(v01);
                P[base + 1] = cvt_tf32(v10);
                P[base + 5] = cvt_tf32(v11);
            }
        }
    }
}

// =====================================================================
// Fused per-level kernel: attention + zGEMM(+Zq,LN,GELU) + KV projection.
// 128 blocks x 256 thr; block handles 32 nodes of level lv+1.
// =====================================================================
__global__ __launch_bounds__(256)
void fused_level(const int* __restrict__ preds,     // + lv*4096*16
                 int lvbase,                         // lv*4096 (pred id offset & Hp row base)
                 const float* __restrict__ KVsrc,
                 float* __restrict__ KVdst,
                 const float* __restrict__ QZrow,    // g_QZ + lv*4096*512
                 const uint32_t* __restrict__ W2p,
                 const float* __restrict__ b2,
                 const uint32_t* __restrict__ Wkvp,
                 const float* __restrict__ bkv,
                 const float* __restrict__ gma, const float* __restrict__ bta,
                 float* __restrict__ outp,           // + (lv+1)*4096*1024 + (l+1)*256
                 uint32_t* __restrict__ Hp)          // g_Hp or null
{
    __shared__ int   sp[32][16];
    __shared__ float qs[32][256];
    __shared__ float sattn[32][68];
    __shared__ float redA[32][8], redB[32][8];
    extern __shared__ uint32_t Az[];                 // 8192 u32 = 32KB

    const int t = threadIdx.x, lane = t & 31, warp = t >> 5;
    const int gid = lane >> 2, tig = lane & 3;
    const int m0 = blockIdx.x * 32;

    // ---- load preds + q rows ----  (FIX: preds offset by this block's m0)
    for (int i = t; i < 512; i += 256)
        sp[i >> 4][i & 15] = preds[m0 * 16 + i] - lvbase;
    for (int i = t; i < 2048; i += 256) {
        int m = i >> 6, c4 = i & 63;
        ((float4*)qs[m])[c4] = *(const float4*)(QZrow + (size_t)(m0 + m) * 512 + c4 * 4);
    }
    __syncthreads();

    // ---- phase A: attention (warp per node, 4 nodes/warp) ----
    const int p = lane >> 1, half = lane & 1;
    for (int it = 0; it < 4; it++) {
        int m = warp + it * 8;
        const float4* kv = (const float4*)(KVsrc + (size_t)sp[m][p] * 512 + half * 128);
        const float4* q4 = (const float4*)&qs[m][half * 128];
        float s0 = 0.f, s1 = 0.f;
        #pragma unroll
        for (int j = 0; j < 16; j++) {
            float4 k4 = kv[j], qq = q4[j];
            s0 += k4.x*qq.x + k4.y*qq.y + k4.z*qq.z + k4.w*qq.w;
        }
        #pragma unroll
        for (int j = 16; j < 32; j++) {
            float4 k4 = kv[j], qq = q4[j];
            s1 += k4.x*qq.x + k4.y*qq.y + k4.z*qq.z + k4.w*qq.w;
        }
        s0 *= 0.125f; s1 *= 0.125f;
        float m0x = s0, m1x = s1;
        #pragma unroll
        for (int o = 2; o <= 16; o <<= 1) {
            m0x = fmaxf(m0x, __shfl_xor_sync(0xffffffffu, m0x, o));
            m1x = fmaxf(m1x, __shfl_xor_sync(0xffffffffu, m1x, o));
        }
        float e0 = expf(s0 - m0x), e1 = expf(s1 - m1x);
        float t0 = e0, t1 = e1;
        #pragma unroll
        for (int o = 2; o <= 16; o <<= 1) {
            t0 += __shfl_xor_sync(0xffffffffu, t0, o);
            t1 += __shfl_xor_sync(0xffffffffu, t1, o);
        }
        sattn[m][(2*half)*16 + p]     = e0 / t0;
        sattn[m][(2*half+1)*16 + p]   = e1 / t1;
        __syncwarp();
        float o0[4], o1[4];
        #pragma unroll
        for (int h = 0; h < 4; h++) { o0[h] = 0.f; o1[h] = 0.f; }
        #pragma unroll
        for (int pp = 0; pp < 16; pp++) {
            const float* vrow = KVsrc + (size_t)sp[m][pp] * 512 + 256;
            #pragma unroll
            for (int h = 0; h < 4; h++) {
                float w = sattn[m][h*16 + pp];
                o0[h] = fmaf(w, vrow[h*64 + lane],      o0[h]);
                o1[h] = fmaf(w, vrow[h*64 + lane + 32], o1[h]);
            }
        }
        #pragma unroll
        for (int h = 0; h < 4; h++) {
            Az[pidx(m, h*64 + lane,      2)] = cvt_tf32(o0[h]);
            Az[pidx(m, h*64 + lane + 32, 2)] = cvt_tf32(o1[h]);
        }
        __syncwarp();
    }
    __syncthreads();

    // ---- phase B: zGEMM (warp tile 32x32, warp = col group) ----
    float accz[2][4][4];
    #pragma unroll
    for (int i = 0; i < 2; i++)
        #pragma unroll
        for (int j = 0; j < 4; j++)
            #pragma unroll
            for (int q = 0; q < 4; q++) accz[i][j][q] = 0.f;

    #pragma unroll 1
    for (int kc = 0; kc < 8; kc++) {
        uint2 bfr[4][4];
        #pragma unroll
        for (int ks = 0; ks < 4; ks++)
            #pragma unroll
            for (int nf = 0; nf < 4; nf++)
                bfr[ks][nf] = ((const uint2*)W2p)[((kc*32 + warp*4 + nf)*4 + ks)*32 + lane];
        #pragma unroll
        for (int ks = 0; ks < 4; ks++) {
            uint4 a0 = ((const uint4*)Az)[((kc*2 + 0)*4 + ks)*32 + lane];
            uint4 a1 = ((const uint4*)Az)[((kc*2 + 1)*4 + ks)*32 + lane];
            #pragma unroll
            for (int nf = 0; nf < 4; nf++) {
                mma_tf32(accz[0][nf], a0, bfr[ks][nf]);
                mma_tf32(accz[1][nf], a1, bfr[ks][nf]);
            }
        }
    }

    // ---- epilogue: +b2+Zq, LN, GELU; write out, Az (perm), Hp (perm) ----
    #pragma unroll
    for (int mf = 0; mf < 2; mf++) {
        int rlo = mf * 16 + gid, rhi = rlo + 8;
        #pragma unroll
        for (int nf = 0; nf < 4; nf++) {
            int col = warp * 32 + nf * 8 + tig * 2;
            float b0 = b2[col], b1 = b2[col + 1];
            float2 zl = *(const float2*)(QZrow + (size_t)(m0 + rlo) * 512 + 256 + col);
            float2 zh = *(const float2*)(QZrow + (size_t)(m0 + rhi) * 512 + 256 + col);
            accz[mf][nf][0] += b0 + zl.x;
            accz[mf][nf][1] += b1 + zl.y;
            accz[mf][nf][2] += b0 + zh.x;
            accz[mf][nf][3] += b1 + zh.y;
        }
    }
    #pragma unroll
    for (int mf = 0; mf < 2; mf++)
        #pragma unroll
        for (int rh = 0; rh < 2; rh++) {
            float s1 = 0.f, s2 = 0.f;
            #pragma unroll
            for (int nf = 0; nf < 4; nf++) {
                float z0 = accz[mf][nf][2*rh], z1 = accz[mf][nf][2*rh + 1];
                s1 += z0 + z1;
                s2 += z0*z0 + z1*z1;
            }
            s1 += __shfl_xor_sync(0xffffffffu, s1, 1);
            s2 += __shfl_xor_sync(0xffffffffu, s2, 1);
            s1 += __shfl_xor_sync(0xffffffffu, s1, 2);
            s2 += __shfl_xor_sync(0xffffffffu, s2, 2);
            if (tig == 0) {
                int rowL = mf * 16 + rh * 8 + gid;
                redA[rowL][warp] = s1;
                redB[rowL][warp] = s2;
            }
        }
    __syncthreads();   // also guarantees all warps finished reading Az
    #pragma unroll
    for (int mf = 0; mf < 2; mf++)
        #pragma unroll
        for (int rh = 0; rh < 2; rh++) {
            int rowL = mf * 16 + rh * 8 + gid;
            float a = 0.f, b = 0.f;
            #pragma unroll
            for (int w = 0; w < 8; w++) { a += redA[rowL][w]; b += redB[rowL][w]; }
            float mu   = a * (1.f / 256.f);
            float var  = b * (1.f / 256.f) - mu * mu;
            float rstd = rsqrtf(var + LN_EPS);
            #pragma unroll
            for (int nf = 0; nf < 4; nf++) {
                int col = warp * 32 + nf * 8 + tig * 2;
                float z0 = (accz[mf][nf][2*rh]     - mu) * rstd * gma[col]     + bta[col];
                float z1 = (accz[mf][nf][2*rh + 1] - mu) * rstd * gma[col + 1] + bta[col + 1];
                float g0 = 0.5f * z0 * (1.f + erff(z0 * 0.70710678118654752f));
                float g1 = 0.5f * z1 * (1.f + erff(z1 * 0.70710678118654752f));
                ((float2*)(outp + (size_t)(m0 + rowL) * 1024))[col >> 1] =
                    make_float2(g0, g1);
                uint32_t c0 = cvt_tf32(g0), c1 = cvt_tf32(g1);
                int base = pidx(rowL, col, 2);
                Az[base] = c0; Az[base + 4] = c1;
                if (Hp) {
                    int gb = pidx(lvbase + m0 + rowL, col, 3840);
                    Hp[gb] = c0; Hp[gb + 4] = c1;
                }
            }
        }
    __syncthreads();

    // ---- phase C: KV projection (warp tile 32x64) ----
    float acck[2][8][4];
    #pragma unroll
    for (int i = 0; i < 2; i++)
        #pragma unroll
        for (int j = 0; j < 8; j++)
            #pragma unroll
            for (int q = 0; q < 4; q++) acck[i][j][q] = 0.f;

    #pragma unroll 1
    for (int kc = 0; kc < 8; kc++) {
        #pragma unroll
        for (int ks = 0; ks < 4; ks++) {
            uint2 bk[8];
            #pragma unroll
            for (int nf = 0; nf < 8; nf++)
                bk[nf] = ((const uint2*)Wkvp)[((kc*64 + warp*8 + nf)*4 + ks)*32 + lane];
            uint4 a0 = ((const uint4*)Az)[((kc*2 + 0)*4 + ks)*32 + lane];
            uint4 a1 = ((const uint4*)Az)[((kc*2 + 1)*4 + ks)*32 + lane];
            #pragma unroll
            for (int nf = 0; nf < 8; nf++) {
                mma_tf32(acck[0][nf], a0, bk[nf]);
                mma_tf32(acck[1][nf], a1, bk[nf]);
            }
        }
    }
    #pragma unroll
    for (int mf = 0; mf < 2; mf++) {
        int r0 = m0 + mf * 16 + gid;
        #pragma unroll
        for (int nf = 0; nf < 8; nf++) {
            int col = warp * 64 + nf * 8 + tig * 2;
            float b0 = bkv[col], b1 = bkv[col + 1];
            *(float2*)(KVdst + (size_t)r0 * 512 + col) =
                make_float2(acck[mf][nf][0] + b0, acck[mf][nf][1] + b1);
            *(float2*)(KVdst + (size_t)(r0 + 8) * 512 + col) =
                make_float2(acck[mf][nf][2] + b0, acck[mf][nf][3] + b1);
        }
    }
}

// ---------------- final level-0 copies ----------------
__global__ __launch_bounds__(256)
void copy0(float* __restrict__ out)
{
    int idx = blockIdx.x * 256 + threadIdx.x;   // 4096*256
    int n = idx >> 8, c = idx & 255;
    float v = out[(size_t)n * 1024 + c];
    out[(size_t)n * 1024 + 256 + c] = v;
    out[(size_t)n * 1024 + 512 + c] = v;
    out[(size_t)n * 1024 + 768 + c] = v;
}

// ---------------- host driver ----------------
extern "C" void kernel_launch(void* const* d_in, const int* in_sizes, int n_in,
                              void* d_out, int out_size)
{
    const float* x        = (const float*)d_in[0];
    const int*   preds_lv = (const int*)d_in[3];
    const float* W_in = (const float*)d_in[4];
    const float* b_in = (const float*)d_in[5];
    const float* Wq   = (const float*)d_in[6];
    const float* bq   = (const float*)d_in[7];
    const float* Wk   = (const float*)d_in[8];
    const float* bk   = (const float*)d_in[9];
    const float* Wv   = (const float*)d_in[10];
    const float* bv   = (const float*)d_in[11];
    const float* Wo   = (const float*)d_in[12];
    const float* bo   = (const float*)d_in[13];
    const float* Wc   = (const float*)d_in[14];
    const float* bc   = (const float*)d_in[15];
    const float* ln_g = (const float*)d_in[16];
    const float* ln_b = (const float*)d_in[17];
    float* out = (float*)d_out;

    float *pQZ, *pKV0, *pWkv, *pbkv, *pWqc, *pbqc, *pW2, *pb2;
    uint32_t *pXp, *pHp, *pHp0, *pWkvp, *pWqcp, *pW2p, *pWinp;
    cudaGetSymbolAddress((void**)&pQZ,   g_QZ);
    cudaGetSymbolAddress((void**)&pKV0,  g_KV);
    cudaGetSymbolAddress((void**)&pWkv,  g_Wkv);
    cudaGetSymbolAddress((void**)&pbkv,  g_bkv);
    cudaGetSymbolAddress((void**)&pWqc,  g_Wqc);
    cudaGetSymbolAddress((void**)&pbqc,  g_bqc);
    cudaGetSymbolAddress((void**)&pW2,   g_W2);
    cudaGetSymbolAddress((void**)&pb2,   g_b2);
    cudaGetSymbolAddress((void**)&pXp,   g_Xp);
    cudaGetSymbolAddress((void**)&pHp,   g_Hp);
    cudaGetSymbolAddress((void**)&pHp0,  g_Hp0);
    cudaGetSymbolAddress((void**)&pWkvp, g_Wkvp);
    cudaGetSymbolAddress((void**)&pWqcp, g_Wqcp);
    cudaGetSymbolAddress((void**)&pW2p,  g_W2p);
    cudaGetSymbolAddress((void**)&pWinp, g_Winp);

    static bool attr_done = false;
    if (!attr_done) {
        cudaFuncSetAttribute((const void*)fused_level,
                             cudaFuncAttributeMaxDynamicSharedMemorySize, 32768);
        attr_done = true;
    }

    // weight prep + permutes
    prep_stack<<<dim3(512, 2, LAYERS), 256>>>(Wq, bq, Wc, Wk, bk, Wv, bv);
    prep_fold<<<dim3(16, 16, LAYERS), dim3(16, 16)>>>(Wc, Wo);
    prep_b2<<<LAYERS, 256>>>(Wc, bo, bc);
    permW<<<dim3(256, 1), 256>>>(W_in, pWinp, 256, 32, 0, 0);
    permW<<<dim3(512, LAYERS), 256>>>(pWqc, pWqcp, 512, 64, 512*256, 512*256);
    permW<<<dim3(512, LAYERS), 256>>>(pWkv, pWkvp, 512, 64, 512*256, 512*256);
    permW<<<dim3(256, LAYERS), 256>>>(pW2,  pW2p,  256, 32, 256*256, 256*256);
    permX<<<NTOT, 256>>>(x, pXp, 4096);

    // h0 = x @ W_in^T + b_in -> out[:,0:256] + permuted copies
    gemm_perm<<<dim3(4, NTOT/128), 256>>>(pXp, 4096, pWinp, 32, b_in,
                                          out, 1024, pHp0, pHp);

    for (int l = 0; l < LAYERS; l++) {
        // [Qh | q@Wc1^T] for all non-source nodes from h_l (permuted in g_Hp)
        gemm_perm<<<dim3(8, NB/128), 256>>>(pHp, 3840,
                                            pWqcp + (size_t)l*512*256, 64,
                                            pbqc + l*512, pQZ, 512,
                                            (uint32_t*)0, (uint32_t*)0);
        // K|V of level 0 (h_l level0 == h0 level0)
        gemm_perm<<<dim3(8, MNODES/128), 256>>>(pHp0, 256,
                                                pWkvp + (size_t)l*512*256, 64,
                                                pbkv + l*512,
                                                pKV0, 512,
                                                (uint32_t*)0, (uint32_t*)0);
        for (int lv = 0; lv < NLEV - 1; lv++) {
            float* KVsrc = pKV0 + (size_t)(lv & 1) * MNODES * 512;
            float* KVdst = pKV0 + (size_t)((lv + 1) & 1) * MNODES * 512;
            fused_level<<<MNODES/32, 256, 32768>>>(
                preds_lv + (size_t)lv * MNODES * 16,
                lv * MNODES,
                KVsrc, KVdst,
                pQZ + (size_t)lv * MNODES * 512,
                pW2p + (size_t)l*256*256, pb2 + l*256,
                pWkvp + (size_t)l*512*256, pbkv + l*512,
                ln_g + l*256, ln_b + l*256,
                out + (size_t)(lv + 1) * MNODES * 1024 + (size_t)(l + 1) * 256,
                (l < LAYERS - 1) ? pHp : (uint32_t*)0);
        }
    }
    copy0<<<4096, 256>>>(out);
}

// round 7
// speedup vs baseline: 1.9352x; 1.0386x over previous
#include <cuda_runtime.h>
#include <cuda_bf16.h>
#include <math.h>
#include <stdint.h>

#define MNODES 4096
#define NLEV   16
#define NTOT   65536
#define HID    256
#define PRED   16
#define HEADS  4
#define HD     64
#define LAYERS 3
#define NB     61440
#define LN_EPS 1e-5f

// ---------------- device scratch ----------------
__device__ __align__(16) float    g_QZ[(size_t)NB * 512];        // [Qh | q@Wc1^T] fp32
__device__ __align__(16) float    g_KV[2][(size_t)MNODES * 512]; // ping-pong [K|V] fp32
__device__ __align__(16) uint32_t g_Xp[(size_t)NTOT * 256];      // x permuted tf32
__device__ __align__(16) uint32_t g_Hp[(size_t)NB * 256];        // h_l rows 4096.. permuted
__device__ __align__(16) uint32_t g_Hp0[(size_t)MNODES * 256];   // h level-0 rows permuted
__device__ __align__(16) float    g_Wkv[LAYERS * 512 * 256];     // stacked fp32 (staging)
__device__ __align__(16) float    g_bkv[LAYERS * 512];
__device__ __align__(16) float    g_Wqc[LAYERS * 512 * 256];
__device__ __align__(16) float    g_bqc[LAYERS * 512];
__device__ __align__(16) float    g_W2 [LAYERS * 256 * 256];
__device__ __align__(16) float    g_b2 [LAYERS * 256];
__device__ __align__(16) uint32_t g_Wkvp[LAYERS * 512 * 256];    // permuted tf32
__device__ __align__(16) uint32_t g_Wqcp[LAYERS * 512 * 256];
__device__ __align__(16) uint32_t g_W2p [LAYERS * 256 * 256];
__device__ __align__(16) uint32_t g_Winp[256 * 256];

// ---------------- helpers ----------------
__device__ __forceinline__ uint32_t cvt_tf32(float x) {
    uint32_t r; asm("cvt.rna.tf32.f32 %0, %1;" : "=r"(r) : "f"(x)); return r;
}
__device__ __forceinline__ void mma_tf32(float c[4], const uint4& a, const uint2& b) {
    asm volatile(
        "mma.sync.aligned.m16n8k8.row.col.f32.tf32.tf32.f32 "
        "{%0,%1,%2,%3}, {%4,%5,%6,%7}, {%8,%9}, {%0,%1,%2,%3};"
        : "+f"(c[0]), "+f"(c[1]), "+f"(c[2]), "+f"(c[3])
        : "r"(a.x), "r"(a.y), "r"(a.z), "r"(a.w), "r"(b.x), "r"(b.y));
}
// permuted A layout (u32 index) for element (row, k), K=256 total
__device__ __forceinline__ int pidx(int row, int k, int mgTot) {
    int kc = k >> 5, ks = (k >> 3) & 3;
    return ((kc * mgTot + (row >> 4)) * 4 + ks) * 128
         + (row & 7) * 16 + (k & 3) * 4 + ((row >> 3) & 1) + 2 * ((k >> 2) & 1);
}
// permuted B layout (u32 index) for element (n, k)
__device__ __forceinline__ int bidx(int n, int k, int ngTot) {
    int kc = k >> 5, ks = (k >> 3) & 3;
    return (((kc * ngTot + (n >> 3)) * 4 + ks) * 32 + (n & 7) * 4 + (k & 3)) * 2
         + ((k >> 2) & 1);
}

// ---------------- weight prep ----------------
__global__ void prep_stack(const float* __restrict__ Wq, const float* __restrict__ bq,
                           const float* __restrict__ Wc,
                           const float* __restrict__ Wk, const float* __restrict__ bk,
                           const float* __restrict__ Wv, const float* __restrict__ bv)
{
    int r = blockIdx.x, which = blockIdx.y, l = blockIdx.z, t = threadIdx.x;
    if (which == 0) {
        if (r < 256) {
            g_Wkv[((size_t)l*512 + r)*256 + t] = Wk[((size_t)l*256 + r)*256 + t];
            if (t == 0) g_bkv[l*512 + r] = bk[l*256 + r];
        } else {
            g_Wkv[((size_t)l*512 + r)*256 + t] = Wv[((size_t)l*256 + r-256)*256 + t];
            if (t == 0) g_bkv[l*512 + r] = bv[l*256 + r-256];
        }
    } else {
        if (r < 256) {
            g_Wqc[((size_t)l*512 + r)*256 + t] = Wq[((size_t)l*256 + r)*256 + t];
            if (t == 0) g_bqc[l*512 + r] = bq[l*256 + r];
        } else {
            g_Wqc[((size_t)l*512 + r)*256 + t] = Wc[((size_t)l*256 + (r-256))*512 + t];
            if (t == 0) g_bqc[l*512 + r] = 0.f;
        }
    }
}
__global__ void prep_fold(const float* __restrict__ Wc, const float* __restrict__ Wo)
{
    int l = blockIdx.z;
    int o = blockIdx.y * 16 + threadIdx.y;
    int i = blockIdx.x * 16 + threadIdx.x;
    const float* wc2 = Wc + ((size_t)l*256 + o)*512 + 256;
    float acc = 0.f;
    for (int j = 0; j < 256; j++)
        acc += wc2[j] * Wo[((size_t)l*256 + j)*256 + i];
    g_W2[((size_t)l*256 + o)*256 + i] = acc;
}
__global__ void prep_b2(const float* __restrict__ Wc, const float* __restrict__ bo,
                        const float* __restrict__ bc)
{
    int l = blockIdx.x, o = threadIdx.x;
    const float* wc2 = Wc + ((size_t)l*256 + o)*512 + 256;
    float acc = bc[l*256 + o];
    for (int j = 0; j < 256; j++)
        acc += wc2[j] * bo[l*256 + j];
    g_b2[l*256 + o] = acc;
}
// permute a [N,256] fp32 row-major weight into tf32 fragment order
__global__ void permW(const float* __restrict__ src, uint32_t* __restrict__ dst,
                      int N, int ngTot, int srcStride, int dstStride)
{
    int l = blockIdx.y;
    int idx = blockIdx.x * 256 + threadIdx.x;
    if (idx >= N * 256) return;
    int n = idx >> 8, k = idx & 255;
    dst[(size_t)l * dstStride + bidx(n, k, ngTot)] =
        cvt_tf32(src[(size_t)l * srcStride + (size_t)n * 256 + k]);
}
// permute activations [M,256] fp32 into tf32 fragment order
__global__ void permX(const float* __restrict__ src, uint32_t* __restrict__ dst, int mgTot)
{
    int idx = blockIdx.x * 256 + threadIdx.x;
    int row = idx >> 8, k = idx & 255;
    dst[pidx(row, k, mgTot)] = cvt_tf32(src[(size_t)row * 256 + k]);
}

// =====================================================================
// GEMM on pre-permuted operands: C[M,N] = A @ B^T + bias
// BM=128, BN=64, 256 thr (8 warps, 4M x 2N). Smem staging = plain uint4 copies.
// Optional permuted-A outputs (row<4096 -> P0, else P1).
// =====================================================================
__global__ __launch_bounds__(256)
void gemm_perm(const uint32_t* __restrict__ Ap, int mgTot,
               const uint32_t* __restrict__ Bp, int ngTot,
               const float* __restrict__ bias,
               float* __restrict__ C, int ldc,
               uint32_t* __restrict__ P0, uint32_t* __restrict__ P1)
{
    __shared__ uint32_t As[2][4096];
    __shared__ uint32_t Bs[2][2048];
    const int t = threadIdx.x, lane = t & 31, warp = t >> 5;
    const int warpN = warp & 1, warpM = warp >> 1;
    const int gid = lane >> 2, tig = lane & 3;
    const int bm = blockIdx.y * 128, bn = blockIdx.x * 64;
    const int mg0 = bm >> 4, ng0 = bn >> 3;

    float acc[2][4][4];
    #pragma unroll
    for (int i = 0; i < 2; i++)
        #pragma unroll
        for (int j = 0; j < 4; j++)
            #pragma unroll
            for (int q = 0; q < 4; q++) acc[i][j][q] = 0.f;

    uint4 aR[4], bR[2];
    auto loadG = [&](int kc) {
        #pragma unroll
        for (int i = 0; i < 4; i++) {
            int idx = t + i * 256;
            int mgl = idx >> 7, r = idx & 127;
            aR[i] = ((const uint4*)Ap)[(size_t)(kc * mgTot + mg0 + mgl) * 128 + r];
        }
        #pragma unroll
        for (int i = 0; i < 2; i++) {
            int idx = t + i * 256;
            int ngl = idx >> 6, r = idx & 63;
            bR[i] = ((const uint4*)Bp)[(size_t)(kc * ngTot + ng0 + ngl) * 64 + r];
        }
    };
    auto storeS = [&](int buf) {
        #pragma unroll
        for (int i = 0; i < 4; i++) ((uint4*)As[buf])[t + i * 256] = aR[i];
        #pragma unroll
        for (int i = 0; i < 2; i++) ((uint4*)Bs[buf])[t + i * 256] = bR[i];
    };
    auto compute = [&](int buf) {
        #pragma unroll
        for (int ks = 0; ks < 4; ks++) {
            uint4 a[2]; uint2 b[4];
            #pragma unroll
            for (int mf = 0; mf < 2; mf++)
                a[mf] = ((const uint4*)As[buf])[((warpM * 2 + mf) * 4 + ks) * 32 + lane];
            #pragma unroll
            for (int nf = 0; nf < 4; nf++)
                b[nf] = ((const uint2*)Bs[buf])[((warpN * 4 + nf) * 4 + ks) * 32 + lane];
            #pragma unroll
            for (int mf = 0; mf < 2; mf++)
                #pragma unroll
                for (int nf = 0; nf < 4; nf++)
                    mma_tf32(acc[mf][nf], a[mf], b[nf]);
        }
    };

    loadG(0); storeS(0); __syncthreads();
    #pragma unroll 1
    for (int kc = 0; kc < 8; kc++) {
        int cur = kc & 1;
        if (kc < 7) loadG(kc + 1);
        compute(cur);
        if (kc < 7) { storeS(1 - cur); __syncthreads(); }
    }

    #pragma unroll
    for (int mf = 0; mf < 2; mf++) {
        int r0 = bm + warpM * 32 + mf * 16 + gid;
        #pragma unroll
        for (int nf = 0; nf < 4; nf++) {
            int c0 = bn + warpN * 32 + nf * 8 + tig * 2;
            float bx = bias ? bias[c0] : 0.f, by = bias ? bias[c0 + 1] : 0.f;
            float v00 = acc[mf][nf][0] + bx, v01 = acc[mf][nf][1] + by;
            float v10 = acc[mf][nf][2] + bx, v11 = acc[mf][nf][3] + by;
            *(float2*)(C + (size_t)r0 * ldc + c0)       = make_float2(v00, v01);
            *(float2*)(C + (size_t)(r0 + 8) * ldc + c0) = make_float2(v10, v11);
            if (P0) {
                uint32_t* P = (r0 < 4096) ? P0 : P1;
                int rr   = (r0 < 4096) ? r0 : r0 - 4096;
                int mgT  = (r0 < 4096) ? 256 : 3840;
                int base = pidx(rr, c0, mgT);
                P[base]     = cvt_tf32(v00);
                P[base + 4] = cvt_tf32(v01);
                P[base + 1] = cvt_tf32(v10);
                P[base + 5] = cvt_tf32(v11);
            }
        }
    }
}

// =====================================================================
// Fused per-level kernel: attention + zGEMM(+Zq,LN,GELU) + KV projection.
// 256 blocks x 256 thr; block handles 16 nodes of level lv+1.
// =====================================================================
__global__ __launch_bounds__(256)
void fused_level(const int* __restrict__ preds,     // + lv*4096*16
                 int lvbase,                         // lv*4096
                 const float* __restrict__ KVsrc,
                 float* __restrict__ KVdst,
                 const float* __restrict__ QZrow,    // g_QZ + lv*4096*512
                 const uint32_t* __restrict__ W2p,
                 const float* __restrict__ b2,
                 const uint32_t* __restrict__ Wkvp,
                 const float* __restrict__ bkv,
                 const float* __restrict__ gma, const float* __restrict__ bta,
                 float* __restrict__ outp,           // + (lv+1)*4096*1024 + (l+1)*256
                 uint32_t* __restrict__ Hp)          // g_Hp or null
{
    __shared__ int   sp[16][16];
    __shared__ float qs[16][256];
    __shared__ float sattn[16][68];
    __shared__ float redA[16][8], redB[16][8];
    extern __shared__ uint32_t Az[];                 // 4096 u32 = 16KB

    const int t = threadIdx.x, lane = t & 31, warp = t >> 5;
    const int gid = lane >> 2, tig = lane & 3;
    const int m0 = blockIdx.x * 16;

    // ---- load preds + q rows ----
    sp[t >> 4][t & 15] = preds[m0 * 16 + t] - lvbase;
    for (int i = t; i < 1024; i += 256) {
        int m = i >> 6, c4 = i & 63;
        ((float4*)qs[m])[c4] = *(const float4*)(QZrow + (size_t)(m0 + m) * 512 + c4 * 4);
    }
    __syncthreads();

    // ---- phase A: attention (warp per node, 2 nodes/warp) ----
    const int p = lane >> 1, half = lane & 1;
    const int hlo = lane >> 4, hhi = 2 + hlo;    // heads for V float4 slices
    for (int it = 0; it < 2; it++) {
        int m = warp + it * 8;
        const float4* kv = (const float4*)(KVsrc + (size_t)sp[m][p] * 512 + half * 128);
        const float4* q4 = (const float4*)&qs[m][half * 128];
        float s0 = 0.f, s1 = 0.f;
        #pragma unroll
        for (int j = 0; j < 16; j++) {
            float4 k4 = kv[j], qq = q4[j];
            s0 += k4.x*qq.x + k4.y*qq.y + k4.z*qq.z + k4.w*qq.w;
        }
        #pragma unroll
        for (int j = 16; j < 32; j++) {
            float4 k4 = kv[j], qq = q4[j];
            s1 += k4.x*qq.x + k4.y*qq.y + k4.z*qq.z + k4.w*qq.w;
        }
        s0 *= 0.125f; s1 *= 0.125f;
        float m0x = s0, m1x = s1;
        #pragma unroll
        for (int o = 2; o <= 16; o <<= 1) {
            m0x = fmaxf(m0x, __shfl_xor_sync(0xffffffffu, m0x, o));
            m1x = fmaxf(m1x, __shfl_xor_sync(0xffffffffu, m1x, o));
        }
        float e0 = expf(s0 - m0x), e1 = expf(s1 - m1x);
        float t0 = e0, t1 = e1;
        #pragma unroll
        for (int o = 2; o <= 16; o <<= 1) {
            t0 += __shfl_xor_sync(0xffffffffu, t0, o);
            t1 += __shfl_xor_sync(0xffffffffu, t1, o);
        }
        sattn[m][(2*half)*16 + p]   = e0 / t0;
        sattn[m][(2*half+1)*16 + p] = e1 / t1;
        __syncwarp();

        // V aggregation, vectorized: lane owns elems [lane*4, +4) and [128+lane*4, +4)
        float4 alo = make_float4(0.f, 0.f, 0.f, 0.f);
        float4 ahi = make_float4(0.f, 0.f, 0.f, 0.f);
        #pragma unroll
        for (int pp = 0; pp < 16; pp++) {
            const float4* vr = (const float4*)(KVsrc + (size_t)sp[m][pp] * 512 + 256);
            float wl = sattn[m][hlo*16 + pp], wh = sattn[m][hhi*16 + pp];
            float4 v0 = vr[lane];
            float4 v1 = vr[32 + lane];
            alo.x = fmaf(wl, v0.x, alo.x); alo.y = fmaf(wl, v0.y, alo.y);
            alo.z = fmaf(wl, v0.z, alo.z); alo.w = fmaf(wl, v0.w, alo.w);
            ahi.x = fmaf(wh, v1.x, ahi.x); ahi.y = fmaf(wh, v1.y, ahi.y);
            ahi.z = fmaf(wh, v1.z, ahi.z); ahi.w = fmaf(wh, v1.w, ahi.w);
        }
        int b0 = pidx(m, lane * 4, 1);
        Az[b0]      = cvt_tf32(alo.x); Az[b0 + 4]  = cvt_tf32(alo.y);
        Az[b0 + 8]  = cvt_tf32(alo.z); Az[b0 + 12] = cvt_tf32(alo.w);
        int b1 = pidx(m, 128 + lane * 4, 1);
        Az[b1]      = cvt_tf32(ahi.x); Az[b1 + 4]  = cvt_tf32(ahi.y);
        Az[b1 + 8]  = cvt_tf32(ahi.z); Az[b1 + 12] = cvt_tf32(ahi.w);
    }
    __syncthreads();

    // ---- phase B: zGEMM (warp tile 16x32) ----
    float accz[4][4];
    #pragma unroll
    for (int j = 0; j < 4; j++)
        #pragma unroll
        for (int q = 0; q < 4; q++) accz[j][q] = 0.f;

    #pragma unroll 1
    for (int kc = 0; kc < 8; kc++) {
        uint2 bfr[4][4];
        #pragma unroll
        for (int ks = 0; ks < 4; ks++)
            #pragma unroll
            for (int nf = 0; nf < 4; nf++)
                bfr[ks][nf] = ((const uint2*)W2p)[((kc*32 + warp*4 + nf)*4 + ks)*32 + lane];
        #pragma unroll
        for (int ks = 0; ks < 4; ks++) {
            uint4 a = ((const uint4*)Az)[(kc*4 + ks)*32 + lane];
            #pragma unroll
            for (int nf = 0; nf < 4; nf++)
                mma_tf32(accz[nf], a, bfr[ks][nf]);
        }
    }

    // ---- epilogue: +b2+Zq, LN, GELU; write out, Az (perm), Hp (perm) ----
    #pragma unroll
    for (int nf = 0; nf < 4; nf++) {
        int col = warp * 32 + nf * 8 + tig * 2;
        float b0 = b2[col], b1 = b2[col + 1];
        float2 zl = *(const float2*)(QZrow + (size_t)(m0 + gid) * 512 + 256 + col);
        float2 zh = *(const float2*)(QZrow + (size_t)(m0 + gid + 8) * 512 + 256 + col);
        accz[nf][0] += b0 + zl.x;
        accz[nf][1] += b1 + zl.y;
        accz[nf][2] += b0 + zh.x;
        accz[nf][3] += b1 + zh.y;
    }
    #pragma unroll
    for (int rh = 0; rh < 2; rh++) {
        float s1 = 0.f, s2 = 0.f;
        #pragma unroll
        for (int nf = 0; nf < 4; nf++) {
            float z0 = accz[nf][2*rh], z1 = accz[nf][2*rh + 1];
            s1 += z0 + z1;
            s2 += z0*z0 + z1*z1;
        }
        s1 += __shfl_xor_sync(0xffffffffu, s1, 1);
        s2 += __shfl_xor_sync(0xffffffffu, s2, 1);
        s1 += __shfl_xor_sync(0xffffffffu, s1, 2);
        s2 += __shfl_xor_sync(0xffffffffu, s2, 2);
        if (tig == 0) {
            redA[rh * 8 + gid][warp] = s1;
            redB[rh * 8 + gid][warp] = s2;
        }
    }
    __syncthreads();   // also guarantees all warps finished reading Az
    #pragma unroll
    for (int rh = 0; rh < 2; rh++) {
        int rowL = rh * 8 + gid;
        float a = 0.f, b = 0.f;
        #pragma unroll
        for (int w = 0; w < 8; w++) { a += redA[rowL][w]; b += redB[rowL][w]; }
        float mu   = a * (1.f / 256.f);
        float var  = b * (1.f / 256.f) - mu * mu;
        float rstd = rsqrtf(var + LN_EPS);
        #pragma unroll
        for (int nf = 0; nf < 4; nf++) {
            int col = warp * 32 + nf * 8 + tig * 2;
            float z0 = (accz[nf][2*rh]     - mu) * rstd * gma[col]     + bta[col];
            float z1 = (accz[nf][2*rh + 1] - mu) * rstd * gma[col + 1] + bta[col + 1];
            float g0 = 0.5f * z0 * (1.f + erff(z0 * 0.70710678118654752f));
            float g1 = 0.5f * z1 * (1.f + erff(z1 * 0.70710678118654752f));
            ((float2*)(outp + (size_t)(m0 + rowL) * 1024))[col >> 1] =
                make_float2(g0, g1);
            uint32_t c0 = cvt_tf32(g0), c1 = cvt_tf32(g1);
            int base = pidx(rowL, col, 1);
            Az[base] = c0; Az[base + 4] = c1;
            if (Hp) {
                int gb = pidx(lvbase + m0 + rowL, col, 3840);
                Hp[gb] = c0; Hp[gb + 4] = c1;
            }
        }
    }
    __syncthreads();

    // ---- phase C: KV projection (warp tile 16x64) ----
    float acck[8][4];
    #pragma unroll
    for (int j = 0; j < 8; j++)
        #pragma unroll
        for (int q = 0; q < 4; q++) acck[j][q] = 0.f;

    #pragma unroll 1
    for (int kc = 0; kc < 8; kc++) {
        #pragma unroll
        for (int ks = 0; ks < 4; ks++) {
            uint2 bk[8];
            #pragma unroll
            for (int nf = 0; nf < 8; nf++)
                bk[nf] = ((const uint2*)Wkvp)[((kc*64 + warp*8 + nf)*4 + ks)*32 + lane];
            uint4 a = ((const uint4*)Az)[(kc*4 + ks)*32 + lane];
            #pragma unroll
            for (int nf = 0; nf < 8; nf++)
                mma_tf32(acck[nf], a, bk[nf]);
        }
    }
    {
        int r0 = m0 + gid;
        #pragma unroll
        for (int nf = 0; nf < 8; nf++) {
            int col = warp * 64 + nf * 8 + tig * 2;
            float b0 = bkv[col], b1 = bkv[col + 1];
            *(float2*)(KVdst + (size_t)r0 * 512 + col) =
                make_float2(acck[nf][0] + b0, acck[nf][1] + b1);
            *(float2*)(KVdst + (size_t)(r0 + 8) * 512 + col) =
                make_float2(acck[nf][2] + b0, acck[nf][3] + b1);
        }
    }
}

// ---------------- final level-0 copies ----------------
__global__ __launch_bounds__(256)
void copy0(float* __restrict__ out)
{
    int idx = blockIdx.x * 256 + threadIdx.x;   // 4096*256
    int n = idx >> 8, c = idx & 255;
    float v = out[(size_t)n * 1024 + c];
    out[(size_t)n * 1024 + 256 + c] = v;
    out[(size_t)n * 1024 + 512 + c] = v;
    out[(size_t)n * 1024 + 768 + c] = v;
}

// ---------------- host driver ----------------
extern "C" void kernel_launch(void* const* d_in, const int* in_sizes, int n_in,
                              void* d_out, int out_size)
{
    const float* x        = (const float*)d_in[0];
    const int*   preds_lv = (const int*)d_in[3];
    const float* W_in = (const float*)d_in[4];
    const float* b_in = (const float*)d_in[5];
    const float* Wq   = (const float*)d_in[6];
    const float* bq   = (const float*)d_in[7];
    const float* Wk   = (const float*)d_in[8];
    const float* bk   = (const float*)d_in[9];
    const float* Wv   = (const float*)d_in[10];
    const float* bv   = (const float*)d_in[11];
    const float* Wo   = (const float*)d_in[12];
    const float* bo   = (const float*)d_in[13];
    const float* Wc   = (const float*)d_in[14];
    const float* bc   = (const float*)d_in[15];
    const float* ln_g = (const float*)d_in[16];
    const float* ln_b = (const float*)d_in[17];
    float* out = (float*)d_out;

    float *pQZ, *pKV0, *pWkv, *pbkv, *pWqc, *pbqc, *pW2, *pb2;
    uint32_t *pXp, *pHp, *pHp0, *pWkvp, *pWqcp, *pW2p, *pWinp;
    cudaGetSymbolAddress((void**)&pQZ,   g_QZ);
    cudaGetSymbolAddress((void**)&pKV0,  g_KV);
    cudaGetSymbolAddress((void**)&pWkv,  g_Wkv);
    cudaGetSymbolAddress((void**)&pbkv,  g_bkv);
    cudaGetSymbolAddress((void**)&pWqc,  g_Wqc);
    cudaGetSymbolAddress((void**)&pbqc,  g_bqc);
    cudaGetSymbolAddress((void**)&pW2,   g_W2);
    cudaGetSymbolAddress((void**)&pb2,   g_b2);
    cudaGetSymbolAddress((void**)&pXp,   g_Xp);
    cudaGetSymbolAddress((void**)&pHp,   g_Hp);
    cudaGetSymbolAddress((void**)&pHp0,  g_Hp0);
    cudaGetSymbolAddress((void**)&pWkvp, g_Wkvp);
    cudaGetSymbolAddress((void**)&pWqcp, g_Wqcp);
    cudaGetSymbolAddress((void**)&pW2p,  g_W2p);
    cudaGetSymbolAddress((void**)&pWinp, g_Winp);

    // weight prep + permutes
    prep_stack<<<dim3(512, 2, LAYERS), 256>>>(Wq, bq, Wc, Wk, bk, Wv, bv);
    prep_fold<<<dim3(16, 16, LAYERS), dim3(16, 16)>>>(Wc, Wo);
    prep_b2<<<LAYERS, 256>>>(Wc, bo, bc);
    permW<<<dim3(256, 1), 256>>>(W_in, pWinp, 256, 32, 0, 0);
    permW<<<dim3(512, LAYERS), 256>>>(pWqc, pWqcp, 512, 64, 512*256, 512*256);
    permW<<<dim3(512, LAYERS), 256>>>(pWkv, pWkvp, 512, 64, 512*256, 512*256);
    permW<<<dim3(256, LAYERS), 256>>>(pW2,  pW2p,  256, 32, 256*256, 256*256);
    permX<<<NTOT, 256>>>(x, pXp, 4096);

    // h0 = x @ W_in^T + b_in -> out[:,0:256] + permuted copies
    gemm_perm<<<dim3(4, NTOT/128), 256>>>(pXp, 4096, pWinp, 32, b_in,
                                          out, 1024, pHp0, pHp);

    for (int l = 0; l < LAYERS; l++) {
        // [Qh | q@Wc1^T] for all non-source nodes from h_l (permuted in g_Hp)
        gemm_perm<<<dim3(8, NB/128), 256>>>(pHp, 3840,
                                            pWqcp + (size_t)l*512*256, 64,
                                            pbqc + l*512, pQZ, 512,
                                            (uint32_t*)0, (uint32_t*)0);
        // K|V of level 0 (h_l level0 == h0 level0)
        gemm_perm<<<dim3(8, MNODES/128), 256>>>(pHp0, 256,
                                                pWkvp + (size_t)l*512*256, 64,
                                                pbkv + l*512,
                                                pKV0, 512,
                                                (uint32_t*)0, (uint32_t*)0);
        for (int lv = 0; lv < NLEV - 1; lv++) {
            float* KVsrc = pKV0 + (size_t)(lv & 1) * MNODES * 512;
            float* KVdst = pKV0 + (size_t)((lv + 1) & 1) * MNODES * 512;
            fused_level<<<MNODES/16, 256, 16384>>>(
                preds_lv + (size_t)lv * MNODES * 16,
                lv * MNODES,
                KVsrc, KVdst,
                pQZ + (size_t)lv * MNODES * 512,
                pW2p + (size_t)l*256*256, pb2 + l*256,
                pWkvp + (size_t)l*512*256, pbkv + l*512,
                ln_g + l*256, ln_b + l*256,
                out + (size_t)(lv + 1) * MNODES * 1024 + (size_t)(l + 1) * 256,
                (l < LAYERS - 1) ? pHp : (uint32_t*)0);
        }
    }
    copy0<<<4096, 256>>>(out);
}